// round 3
// baseline (speedup 1.0000x reference)
#include <cuda_runtime.h>

#define Bz 32
#define Lz 200
#define Dz 768
#define Sz 1556
#define ROWCAP (Bz*Lz)   /* 6400, >= max rows per bucket (6336) */

// ---------------- device scratch (static, no allocs) ----------------
__device__ int  g_offsets[Bz*9];      // per-batch bucket offsets [B][9]
__device__ int  g_rowbase[8*Bz];      // per-k per-batch base into row list
__device__ int  g_Mk[8];              // rows per bucket
__device__ int2 g_rows[8*ROWCAP];     // {src_row=b*L+p, dst_row=b*S+s}
__device__ float g_Wt[35*Dz*Dz];      // transposed weights, 82.6 MB

struct Ptrs7 { const float* p[7]; };

// ---------------- setup: lengths, offsets, per-k bases ----------------
__global__ void setup_kernel(const int* __restrict__ mask) {
    __shared__ int sh_n[Bz];
    int t = threadIdx.x;
    if (t < Bz) {
        int n = 0;
        #pragma unroll 8
        for (int i = 0; i < Lz; i++) n += mask[t*Lz + i];
        sh_n[t] = n;
        int off = 0;
        g_offsets[t*9 + 0] = 0;
        #pragma unroll
        for (int k = 0; k < 8; k++) {
            int c = n - k - 2; if (c < 0) c = 0;
            off += c;
            g_offsets[t*9 + k + 1] = off;
        }
    }
    __syncthreads();
    if (t < 8) {
        int k = t, run = 0;
        for (int b = 0; b < Bz; b++) {
            g_rowbase[k*Bz + b] = run;
            int c = sh_n[b] - k - 2; if (c < 0) c = 0;
            run += c;
        }
        g_Mk[k] = run;
    }
}

// ---------------- bucket/pos per span slot, build row lists ----------------
__global__ void build_rows(float* __restrict__ out_tail, int write_tail) {
    int idx = blockIdx.x * blockDim.x + threadIdx.x;
    if (idx >= Bz*Sz) return;
    int b = idx / Sz, s = idx % Sz;
    const int* off = &g_offsets[b*9];
    int k = 0;
    #pragma unroll
    for (int m = 1; m < 8; m++) k += (off[m] <= s);
    if (s < off[8]) {                      // valid
        int rel = s - off[k];
        int p = rel + 1;
        int r = g_rowbase[k*Bz + b] + rel;
        g_rows[k*ROWCAP + r] = make_int2(b*Lz + p, idx);  // idx == b*S + s
        if (write_tail) out_tail[idx] = 1.0f;  // checker reads tail as float32
    }
    // invalid: output row + tail already zeroed by zero_kernel
}

// ---------------- zero output ----------------
__global__ void zero_kernel(float4* __restrict__ out, int n4) {
    int i = blockIdx.x * blockDim.x + threadIdx.x;
    if (i < n4) out[i] = make_float4(0.f, 0.f, 0.f, 0.f);
}

// ---------------- weight transpose: w[o][i][j] -> Wt[(j*D+i)*D + o] ----------------
__global__ void transpose_w_kernel(Ptrs7 w) {
    int z = blockIdx.z;              // z=0..6 -> width z+2 (w2..w8)
    int width = z + 2;
    int C = Dz * width;
    int c0 = blockIdx.x * 32;
    if (c0 >= C) return;
    int o0 = blockIdx.y * 32;
    __shared__ float tile[32][33];
    const float* __restrict__ src = w.p[z];
    #pragma unroll
    for (int r = 0; r < 4; r++) {
        int o = o0 + threadIdx.y + r*8;
        int c = c0 + threadIdx.x;
        if (c < C) tile[threadIdx.y + r*8][threadIdx.x] = src[(size_t)o*C + c];
    }
    __syncthreads();
    size_t base = (size_t)(z*(z+3)/2) * Dz * Dz;
    #pragma unroll
    for (int r = 0; r < 4; r++) {
        int c = c0 + threadIdx.y + r*8;
        int o = o0 + threadIdx.x;
        if (c < C) {
            int i = c / width, j = c % width;
            g_Wt[base + (size_t)(j*Dz + i)*Dz + o] = tile[threadIdx.x][threadIdx.y + r*8];
        }
    }
}

// ---------------- bucket 0: plain row copy ----------------
__global__ void copy_k0(const float* __restrict__ feat, float* __restrict__ out) {
    int r = blockIdx.x;
    if (r >= g_Mk[0]) return;
    int2 rc = g_rows[r];
    const float4* __restrict__ s = (const float4*)(feat + (size_t)rc.x * Dz);
    float4* __restrict__ d = (float4*)(out + (size_t)rc.y * Dz);
    d[threadIdx.x] = s[threadIdx.x];   // 192 threads * float4 = 768 floats
}

// ---------------- gathered GEMM per bucket k=1..7 ----------------
// C[r, o] = bias[o] + sum_kk A[r,kk] * Wt[kk, o],  A row = contiguous feature window
__global__ __launch_bounds__(256)
void gemm_kernel(const float* __restrict__ feat, Ptrs7 bias, float* __restrict__ out) {
    int z = blockIdx.z;                // bucket k = z+1, conv width z+2
    int Mk = g_Mk[z + 1];
    int row0 = blockIdx.y * 128;
    if (row0 >= Mk) return;
    int width = z + 2;
    int n0 = blockIdx.x * 64;
    int t = threadIdx.x;
    int tx = t & 15, ty = t >> 4;

    __shared__ int s_src[128];
    __shared__ int s_dst[128];
    __shared__ __align__(16) float As[128][20];   // padded stride 20: float4-aligned, conflict-free
    __shared__ __align__(16) float Bs[16][64];

    if (t < 128) {
        int gr = row0 + t;
        if (gr < Mk) {
            int2 rc = g_rows[(z+1)*ROWCAP + gr];
            s_src[t] = rc.x * Dz;
            s_dst[t] = rc.y;
        } else { s_src[t] = 0; s_dst[t] = -1; }
    }
    __syncthreads();

    // hoisted loader coordinates
    int arow0 = t >> 2;                 // rows 0..63 (and +64)
    int ac4   = (t & 3) << 2;
    const float* aptr0 = feat + s_src[arow0]      + ac4;
    const float* aptr1 = feat + s_src[arow0 + 64] + ac4;
    int brow = t >> 4;                  // 0..15
    int bc4  = (t & 15) << 2;
    const float* bptr = g_Wt + (size_t)(z*(z+3)/2)*Dz*Dz + (size_t)brow*Dz + n0 + bc4;

    float acc[8][4];
    #pragma unroll
    for (int i = 0; i < 8; i++) { acc[i][0]=0.f; acc[i][1]=0.f; acc[i][2]=0.f; acc[i][3]=0.f; }

    int steps = width * (Dz / 16);      // K-tiles of 16
    for (int kt = 0; kt < steps; kt++) {
        float4 a0 = *(const float4*)(aptr0 + (size_t)kt*16);
        float4 a1 = *(const float4*)(aptr1 + (size_t)kt*16);
        float4 bv = *(const float4*)(bptr + (size_t)kt*16*Dz);
        __syncthreads();
        *(float4*)&As[arow0][ac4]      = a0;
        *(float4*)&As[arow0 + 64][ac4] = a1;
        *(float4*)&Bs[brow][bc4]       = bv;
        __syncthreads();
        #pragma unroll
        for (int kk = 0; kk < 16; kk++) {
            float4 b4 = *(const float4*)&Bs[kk][tx << 2];
            #pragma unroll
            for (int i = 0; i < 8; i++) {
                float a = As[(ty << 3) + i][kk];
                acc[i][0] += a * b4.x;
                acc[i][1] += a * b4.y;
                acc[i][2] += a * b4.z;
                acc[i][3] += a * b4.w;
            }
        }
    }

    float4 bb = *(const float4*)(bias.p[z] + n0 + (tx << 2));
    #pragma unroll
    for (int i = 0; i < 8; i++) {
        int d = s_dst[(ty << 3) + i];
        if (d >= 0) {
            float4 v;
            v.x = acc[i][0] + bb.x;
            v.y = acc[i][1] + bb.y;
            v.z = acc[i][2] + bb.z;
            v.w = acc[i][3] + bb.w;
            *(float4*)(out + (size_t)d*Dz + n0 + (tx << 2)) = v;
        }
    }
}

// ---------------- launch ----------------
extern "C" void kernel_launch(void* const* d_in, const int* in_sizes, int n_in,
                              void* d_out, int out_size) {
    const float* feat = (const float*)d_in[0];
    const int*   mask = (const int*)d_in[1];
    // d_in[2] = span_mask (all ones, only its shape S matters) — unused

    // Classify inputs 3..16 by element count: bias = 768 elems, weight = k*768*768.
    // Robust to either w2..w8,b2..b8 or interleaved ordering.
    Ptrs7 wp, bp;
    int wi = 0, bi = 0;
    for (int i = 3; i < n_in && i < 17; i++) {
        if (in_sizes[i] == Dz) {
            if (bi < 7) bp.p[bi++] = (const float*)d_in[i];
        } else {
            if (wi < 7) wp.p[wi++] = (const float*)d_in[i];
        }
    }
    float* out = (float*)d_out;

    int n4 = out_size >> 2;
    zero_kernel<<<(n4 + 255) / 256, 256>>>((float4*)d_out, n4);

    setup_kernel<<<1, 64>>>(mask);

    int tail = (out_size >= Bz*Sz*Dz + Bz*Sz) ? 1 : 0;
    build_rows<<<(Bz*Sz + 255) / 256, 256>>>(out + (size_t)Bz*Sz*Dz, tail);

    transpose_w_kernel<<<dim3(192, 24, 7), dim3(32, 8)>>>(wp);

    copy_k0<<<Bz*(Lz - 2), 192>>>(feat, out);

    gemm_kernel<<<dim3(12, 50, 7), 256>>>(feat, bp, out);
}

// round 5
// speedup vs baseline: 2.0060x; 2.0060x over previous
#include <cuda_runtime.h>
#include <cuda_bf16.h>
#include <cstdint>

#define Bz 32
#define Lz 200
#define Dz 768
#define Sz 1556
#define ROWCAP (Bz*Lz)   /* 6400 >= max rows per bucket (6336) */

// ---------------- device scratch (static, no allocs) ----------------
__device__ int  g_offsets[Bz*9];
__device__ int  g_rowbase[8*Bz];
__device__ int  g_Mk[8];
__device__ int2 g_rows[8*ROWCAP];
__device__ __nv_bfloat16 g_featH[Bz*Lz*Dz];       // 9.8MB
__device__ __nv_bfloat16 g_featL[Bz*Lz*Dz];
#define WTOT (35*Dz*Dz)
__device__ __nv_bfloat16 g_WtH[WTOT];             // 41.3MB, K-major [o][kk]
__device__ __nv_bfloat16 g_WtL[WTOT];

struct Ptrs7 { const float* p[7]; };

// ---------------- helpers ----------------
__device__ __forceinline__ uint32_t s2u(const void* p) {
    uint32_t a;
    asm("{ .reg .u64 t; cvta.to.shared.u64 t, %1; cvt.u32.u64 %0, t; }" : "=r"(a) : "l"(p));
    return a;
}
__device__ __forceinline__ void cpasync16(uint32_t s, const void* g) {
    asm volatile("cp.async.cg.shared.global [%0], [%1], 16;" :: "r"(s), "l"(g));
}
__device__ __forceinline__ void ldsm4(uint32_t* r, uint32_t a) {
    asm volatile("ldmatrix.sync.aligned.m8n8.x4.shared.b16 {%0,%1,%2,%3}, [%4];"
        : "=r"(r[0]), "=r"(r[1]), "=r"(r[2]), "=r"(r[3]) : "r"(a));
}
__device__ __forceinline__ void ldsm2(uint32_t* r, uint32_t a) {
    asm volatile("ldmatrix.sync.aligned.m8n8.x2.shared.b16 {%0,%1}, [%2];"
        : "=r"(r[0]), "=r"(r[1]) : "r"(a));
}
__device__ __forceinline__ void mma16816(float* c, const uint32_t* a, const uint32_t* b) {
    asm volatile("mma.sync.aligned.m16n8k16.row.col.f32.bf16.bf16.f32 "
        "{%0,%1,%2,%3}, {%4,%5,%6,%7}, {%8,%9}, {%0,%1,%2,%3};"
        : "+f"(c[0]), "+f"(c[1]), "+f"(c[2]), "+f"(c[3])
        : "r"(a[0]), "r"(a[1]), "r"(a[2]), "r"(a[3]), "r"(b[0]), "r"(b[1]));
}

// ---------------- setup: lengths, offsets, per-k bases ----------------
__global__ void setup_kernel(const int* __restrict__ mask) {
    __shared__ int sh_n[Bz];
    int t = threadIdx.x;
    if (t < Bz) {
        int n = 0;
        #pragma unroll 8
        for (int i = 0; i < Lz; i++) n += mask[t*Lz + i];
        sh_n[t] = n;
        int off = 0;
        g_offsets[t*9 + 0] = 0;
        #pragma unroll
        for (int k = 0; k < 8; k++) {
            int c = n - k - 2; if (c < 0) c = 0;
            off += c;
            g_offsets[t*9 + k + 1] = off;
        }
    }
    __syncthreads();
    if (t < 8) {
        int k = t, run = 0;
        for (int b = 0; b < Bz; b++) {
            g_rowbase[k*Bz + b] = run;
            int c = sh_n[b] - k - 2; if (c < 0) c = 0;
            run += c;
        }
        g_Mk[k] = run;
    }
}

// ---------------- per-slot bucket/pos, build row lists ----------------
__global__ void build_rows(float* __restrict__ out_tail, int write_tail) {
    int idx = blockIdx.x * blockDim.x + threadIdx.x;
    if (idx >= Bz*Sz) return;
    int b = idx / Sz, s = idx % Sz;
    const int* off = &g_offsets[b*9];
    int k = 0;
    #pragma unroll
    for (int m = 1; m < 8; m++) k += (off[m] <= s);
    if (s < off[8]) {
        int rel = s - off[k];
        int p = rel + 1;
        int r = g_rowbase[k*Bz + b] + rel;
        g_rows[k*ROWCAP + r] = make_int2(b*Lz + p, idx);
        if (write_tail) out_tail[idx] = 1.0f;
    }
}

// ---------------- zero output ----------------
__global__ void zero_kernel(float4* __restrict__ out, int n4) {
    int i = blockIdx.x * blockDim.x + threadIdx.x;
    if (i < n4) out[i] = make_float4(0.f, 0.f, 0.f, 0.f);
}

// ---------------- split features into bf16 hi/lo ----------------
__global__ void split_feat(const float* __restrict__ feat) {
    int i = blockIdx.x * 256 + threadIdx.x;
    if (i >= Bz*Lz*Dz) return;
    float v = feat[i];
    __nv_bfloat16 h = __float2bfloat16(v);
    float r = v - __bfloat162float(h);
    g_featH[i] = h;
    g_featL[i] = __float2bfloat16(r);
}

// ---------------- permute + split weights: w[o][i][j] -> Wt[o][kk=j*768+i] ----------------
__global__ void split_w(Ptrs7 w) {
    int z = blockIdx.y; int width = z + 2; int K = Dz * width;
    long idx = (long)blockIdx.x * 256 + threadIdx.x;
    if (idx >= (long)Dz * K) return;
    int o = (int)(idx / K), kk = (int)(idx % K);
    int j = kk / Dz, i = kk - j*Dz;
    float v = w.p[z][(long)o*K + i*width + j];
    __nv_bfloat16 h = __float2bfloat16(v);
    float r = v - __bfloat162float(h);
    long base = (long)(z*(z+3)/2) * Dz * Dz;
    g_WtH[base + idx] = h;
    g_WtL[base + idx] = __float2bfloat16(r);
}

// ---------------- bucket 0: exact fp32 row copy ----------------
__global__ void copy_k0(const float* __restrict__ feat, float* __restrict__ out) {
    int r = blockIdx.x;
    if (r >= g_Mk[0]) return;
    int2 rc = g_rows[r];
    const float4* __restrict__ s = (const float4*)(feat + (size_t)rc.x * Dz);
    float4* __restrict__ d = (float4*)(out + (size_t)rc.y * Dz);
    d[threadIdx.x] = s[threadIdx.x];
}

// ---------------- mma.sync gathered GEMM, buckets k=1..7 ----------------
// Extended-K split: entries e = 0..3*nch-1; term = e%3 -> (AH,BH),(AH,BL),(AL,BH)
// CTA tile 128x128, warp tile 64x32 (2x4 warps), K-chunk 32 bf16, 4-stage cp.async.
#define STAGE_BYTES 20480            /* A 128*80 + B 128*80 */
__global__ void __launch_bounds__(256, 2) mma_gemm(Ptrs7 bias, float* __restrict__ out) {
    int z = blockIdx.z;                 // bucket k = z+1, conv width z+2
    int Mk = g_Mk[z + 1];
    int m0 = blockIdx.y * 128;
    if (m0 >= Mk) return;
    int width = z + 2;
    int Ktot = Dz * width;
    int n0 = blockIdx.x * 128;
    int t = threadIdx.x;
    int w = t >> 5, lane = t & 31;
    int wm = w >> 2, wn = w & 3;        // 2 x 4 warp grid

    __shared__ int s_src[128], s_dst[128];
    extern __shared__ __align__(16) char smem[];
    uint32_t smem_u = s2u(smem);

    if (t < 128) {
        int gr = m0 + t;
        if (gr < Mk) {
            int2 rc = g_rows[(z+1)*ROWCAP + gr];
            s_src[t] = rc.x * Dz;
            s_dst[t] = rc.y;
        } else { s_src[t] = 0; s_dst[t] = -1; }
    }
    __syncthreads();

    // loader: thread t -> rows (t>>2) and 64+(t>>2), 16B chunk q = t&3
    int lrow = t >> 2, q = t & 3;
    const __nv_bfloat16* aH0 = g_featH + s_src[lrow]      + q*8;
    const __nv_bfloat16* aH1 = g_featH + s_src[lrow + 64] + q*8;
    const __nv_bfloat16* aL0 = g_featL + s_src[lrow]      + q*8;
    const __nv_bfloat16* aL1 = g_featL + s_src[lrow + 64] + q*8;
    long wzb = (long)(z*(z+3)/2) * Dz * Dz;
    const __nv_bfloat16* bH0 = g_WtH + wzb + (long)(n0 + lrow)      * Ktot + q*8;
    const __nv_bfloat16* bH1 = g_WtH + wzb + (long)(n0 + lrow + 64) * Ktot + q*8;
    const __nv_bfloat16* bL0 = g_WtL + wzb + (long)(n0 + lrow)      * Ktot + q*8;
    const __nv_bfloat16* bL1 = g_WtL + wzb + (long)(n0 + lrow + 64) * Ktot + q*8;
    uint32_t sA0 = smem_u +         lrow*80 + q*16;
    uint32_t sA1 = sA0 + 64*80;
    uint32_t sB0 = smem_u + 10240 + lrow*80 + q*16;
    uint32_t sB1 = sB0 + 64*80;

    // ldmatrix per-lane offsets
    int l8 = lane & 7;
    uint32_t aLm = smem_u + (wm*64 + l8 + ((lane >> 3) & 1) * 8) * 80 + ((lane >> 4) & 1) * 16;
    uint32_t bLm = smem_u + 10240 + (wn*32 + l8) * 80 + ((lane >> 3) & 1) * 16;

    float acc[4][4][4];
    #pragma unroll
    for (int i = 0; i < 4; i++)
        #pragma unroll
        for (int j = 0; j < 4; j++)
            #pragma unroll
            for (int r = 0; r < 4; r++) acc[i][j][r] = 0.f;

    int E = 3 * (Ktot / 32);
    int ik = 0, it = 0;                 // issue-side k-chunk / term counters

    #pragma unroll 1
    for (int p = 0; p < 3; p++) {
        uint32_t so = p * STAGE_BYTES;
        int ko = ik * 32;
        const __nv_bfloat16* pa0 = (it == 2 ? aL0 : aH0) + ko;
        const __nv_bfloat16* pa1 = (it == 2 ? aL1 : aH1) + ko;
        const __nv_bfloat16* pb0 = (it == 1 ? bL0 : bH0) + ko;
        const __nv_bfloat16* pb1 = (it == 1 ? bL1 : bH1) + ko;
        cpasync16(sA0 + so, pa0); cpasync16(sA1 + so, pa1);
        cpasync16(sB0 + so, pb0); cpasync16(sB1 + so, pb1);
        asm volatile("cp.async.commit_group;" ::: "memory");
        if (++it == 3) { it = 0; ik++; }
    }

    #pragma unroll 1
    for (int e = 0; e < E; e++) {
        int st = e & 3;
        asm volatile("cp.async.wait_group 2;" ::: "memory");
        __syncthreads();
        if (e + 3 < E) {
            uint32_t so = ((e + 3) & 3) * STAGE_BYTES;
            int ko = ik * 32;
            const __nv_bfloat16* pa0 = (it == 2 ? aL0 : aH0) + ko;
            const __nv_bfloat16* pa1 = (it == 2 ? aL1 : aH1) + ko;
            const __nv_bfloat16* pb0 = (it == 1 ? bL0 : bH0) + ko;
            const __nv_bfloat16* pb1 = (it == 1 ? bL1 : bH1) + ko;
            cpasync16(sA0 + so, pa0); cpasync16(sA1 + so, pa1);
            cpasync16(sB0 + so, pb0); cpasync16(sB1 + so, pb1);
            if (++it == 3) { it = 0; ik++; }
        }
        asm volatile("cp.async.commit_group;" ::: "memory");

        uint32_t so = st * STAGE_BYTES;
        #pragma unroll
        for (int s = 0; s < 2; s++) {
            uint32_t kb = s * 32;
            uint32_t a[4][4], b[4][2];
            #pragma unroll
            for (int mf = 0; mf < 4; mf++) ldsm4(a[mf], aLm + so + mf*16*80 + kb);
            #pragma unroll
            for (int nf = 0; nf < 4; nf++) ldsm2(b[nf], bLm + so + nf*8*80 + kb);
            #pragma unroll
            for (int mf = 0; mf < 4; mf++)
                #pragma unroll
                for (int nf = 0; nf < 4; nf++)
                    mma16816(acc[mf][nf], a[mf], b[nf]);
        }
    }
    asm volatile("cp.async.wait_group 0;" ::: "memory");

    // epilogue: bias + scatter to gathered dst rows
    int r0 = wm*64 + (lane >> 2);
    int cb = n0 + wn*32 + ((lane & 3) << 1);
    const float* bpz = bias.p[z];
    #pragma unroll
    for (int mf = 0; mf < 4; mf++) {
        int row = r0 + mf*16;
        int d0 = s_dst[row], d1 = s_dst[row + 8];
        #pragma unroll
        for (int nf = 0; nf < 4; nf++) {
            float2 bv = *(const float2*)(bpz + cb + nf*8);
            if (d0 >= 0) {
                float2 v; v.x = acc[mf][nf][0] + bv.x; v.y = acc[mf][nf][1] + bv.y;
                *(float2*)(out + (long)d0*Dz + cb + nf*8) = v;
            }
            if (d1 >= 0) {
                float2 v; v.x = acc[mf][nf][2] + bv.x; v.y = acc[mf][nf][3] + bv.y;
                *(float2*)(out + (long)d1*Dz + cb + nf*8) = v;
            }
        }
    }
}

// ---------------- launch ----------------
extern "C" void kernel_launch(void* const* d_in, const int* in_sizes, int n_in,
                              void* d_out, int out_size) {
    const float* feat = (const float*)d_in[0];
    const int*   mask = (const int*)d_in[1];
    // d_in[2] = span_mask (unused; shape only)

    // classify by element count: bias = 768 elems, weight = k*768*768 (ascending k)
    Ptrs7 wp, bp;
    int wi = 0, bi = 0;
    for (int i = 3; i < n_in && i < 17; i++) {
        if (in_sizes[i] == Dz) { if (bi < 7) bp.p[bi++] = (const float*)d_in[i]; }
        else                   { if (wi < 7) wp.p[wi++] = (const float*)d_in[i]; }
    }
    float* out = (float*)d_out;

    int n4 = out_size >> 2;
    zero_kernel<<<(n4 + 255) / 256, 256>>>((float4*)d_out, n4);

    setup_kernel<<<1, 64>>>(mask);

    int tail = (out_size >= Bz*Sz*Dz + Bz*Sz) ? 1 : 0;
    build_rows<<<(Bz*Sz + 255) / 256, 256>>>(out + (size_t)Bz*Sz*Dz, tail);

    split_feat<<<(Bz*Lz*Dz + 255) / 256, 256>>>(feat);
    split_w<<<dim3((Dz*Dz*8 + 255) / 256, 7), 256>>>(wp);

    copy_k0<<<Bz*(Lz - 2), 192>>>(feat, out);

    cudaFuncSetAttribute(mma_gemm, cudaFuncAttributeMaxDynamicSharedMemorySize, 4*STAGE_BYTES);
    mma_gemm<<<dim3(6, 50, 7), 256, 4*STAGE_BYTES>>>(bp, out);
}

// round 6
// speedup vs baseline: 2.2780x; 1.1356x over previous
#include <cuda_runtime.h>
#include <cuda_bf16.h>
#include <cstdint>

#define Bz 32
#define Lz 200
#define Dz 768
#define Sz 1556
#define ROWCAP (Bz*Lz)   /* 6400 >= max rows per bucket (6336) */
#define FEATN (Bz*Lz*Dz)
#define WPER  (Dz*Dz)    /* 589824 */

// ---------------- device scratch (static, no allocs) ----------------
__device__ int  g_offsets[Bz*9];
__device__ int  g_rowbase[8*Bz];
__device__ int  g_Mk[8];
__device__ int2 g_rows[8*ROWCAP];
__device__ __nv_bfloat16 g_featH[FEATN];
__device__ __nv_bfloat16 g_featL[FEATN];
#define WTOT (35*WPER)
__device__ __nv_bfloat16 g_WtH[WTOT];             // K-major [z][o][kk]
__device__ __nv_bfloat16 g_WtL[WTOT];

struct Ptrs7 { const float* p[7]; };

// ---------------- helpers ----------------
__device__ __forceinline__ uint32_t s2u(const void* p) {
    uint32_t a;
    asm("{ .reg .u64 t; cvta.to.shared.u64 t, %1; cvt.u32.u64 %0, t; }" : "=r"(a) : "l"(p));
    return a;
}
__device__ __forceinline__ void cpasync16(uint32_t s, const void* g) {
    asm volatile("cp.async.cg.shared.global [%0], [%1], 16;" :: "r"(s), "l"(g));
}
__device__ __forceinline__ void ldsm4(uint32_t* r, uint32_t a) {
    asm volatile("ldmatrix.sync.aligned.m8n8.x4.shared.b16 {%0,%1,%2,%3}, [%4];"
        : "=r"(r[0]), "=r"(r[1]), "=r"(r[2]), "=r"(r[3]) : "r"(a));
}
__device__ __forceinline__ void ldsm2(uint32_t* r, uint32_t a) {
    asm volatile("ldmatrix.sync.aligned.m8n8.x2.shared.b16 {%0,%1}, [%2];"
        : "=r"(r[0]), "=r"(r[1]) : "r"(a));
}
__device__ __forceinline__ void mma16816(float* c, const uint32_t* a, const uint32_t* b) {
    asm volatile("mma.sync.aligned.m16n8k16.row.col.f32.bf16.bf16.f32 "
        "{%0,%1,%2,%3}, {%4,%5,%6,%7}, {%8,%9}, {%0,%1,%2,%3};"
        : "+f"(c[0]), "+f"(c[1]), "+f"(c[2]), "+f"(c[3])
        : "r"(a[0]), "r"(a[1]), "r"(a[2]), "r"(a[3]), "r"(b[0]), "r"(b[1]));
}

// ---------------- fused prep: zero out + split features + split weights ----------------
__global__ void prep(const float* __restrict__ feat, Ptrs7 w,
                     float4* __restrict__ out4, int n4) {
    int stride = gridDim.x * blockDim.x;
    int tid = blockIdx.x * blockDim.x + threadIdx.x;
    for (int i = tid; i < n4; i += stride)
        out4[i] = make_float4(0.f, 0.f, 0.f, 0.f);
    for (int i = tid; i < FEATN; i += stride) {
        float v = feat[i];
        __nv_bfloat16 h = __float2bfloat16(v);
        g_featH[i] = h;
        g_featL[i] = __float2bfloat16(v - __bfloat162float(h));
    }
    for (long i = tid; i < (long)WTOT; i += stride) {
        long r = i; int z = 0;
        while (r >= (long)(z + 2) * WPER) { r -= (long)(z + 2) * WPER; z++; }
        int K = Dz * (z + 2);
        int o = (int)(r / K), kk = (int)(r % K);
        int j = kk / Dz, ii = kk - j * Dz;
        float v = w.p[z][(long)o * K + ii * (z + 2) + j];
        __nv_bfloat16 h = __float2bfloat16(v);
        long dst = (long)(z * (z + 3) / 2) * WPER + r;
        g_WtH[dst] = h;
        g_WtL[dst] = __float2bfloat16(v - __bfloat162float(h));
    }
}

// ---------------- setup: lengths, offsets, per-k bases ----------------
__global__ void setup_kernel(const int* __restrict__ mask) {
    __shared__ int sh_n[Bz];
    int t = threadIdx.x;
    if (t < Bz) {
        int n = 0;
        #pragma unroll 8
        for (int i = 0; i < Lz; i++) n += mask[t*Lz + i];
        sh_n[t] = n;
        int off = 0;
        g_offsets[t*9 + 0] = 0;
        #pragma unroll
        for (int k = 0; k < 8; k++) {
            int c = n - k - 2; if (c < 0) c = 0;
            off += c;
            g_offsets[t*9 + k + 1] = off;
        }
    }
    __syncthreads();
    if (t < 8) {
        int k = t, run = 0;
        for (int b = 0; b < Bz; b++) {
            g_rowbase[k*Bz + b] = run;
            int c = sh_n[b] - k - 2; if (c < 0) c = 0;
            run += c;
        }
        g_Mk[k] = run;
    }
}

// ---------------- per-slot bucket/pos, build row lists ----------------
__global__ void build_rows(float* __restrict__ out_tail, int write_tail) {
    int idx = blockIdx.x * blockDim.x + threadIdx.x;
    if (idx >= Bz*Sz) return;
    int b = idx / Sz, s = idx % Sz;
    const int* off = &g_offsets[b*9];
    int k = 0;
    #pragma unroll
    for (int m = 1; m < 8; m++) k += (off[m] <= s);
    if (s < off[8]) {
        int rel = s - off[k];
        int p = rel + 1;
        int r = g_rowbase[k*Bz + b] + rel;
        g_rows[k*ROWCAP + r] = make_int2(b*Lz + p, idx);
        if (write_tail) out_tail[idx] = 1.0f;
    }
}

// ---------------- bucket 0: exact fp32 row copy ----------------
__global__ void copy_k0(const float* __restrict__ feat, float* __restrict__ out) {
    int r = blockIdx.x;
    if (r >= g_Mk[0]) return;
    int2 rc = g_rows[r];
    const float4* __restrict__ s = (const float4*)(feat + (size_t)rc.x * Dz);
    float4* __restrict__ d = (float4*)(out + (size_t)rc.y * Dz);
    d[threadIdx.x] = s[threadIdx.x];
}

// ---------------- mma.sync gathered GEMM, buckets k=1..7 ----------------
// Per K-chunk(32): stage holds the 4 unique tiles AH,AL,BH,BL (10240B each, 80B rows).
// 3 split terms run from one staged chunk: D += AH*BH + AH*BL + AL*BH.
#define TILE_B 10240
#define STAGE_B 40960
__global__ void __launch_bounds__(256, 2) mma_gemm(Ptrs7 bias, float* __restrict__ out) {
    int z = blockIdx.z;                 // bucket k = z+1, conv width z+2
    int Mk = g_Mk[z + 1];
    int m0 = blockIdx.y * 128;
    if (m0 >= Mk) return;
    int Ktot = Dz * (z + 2);
    int n0 = blockIdx.x * 128;
    int t = threadIdx.x;
    int w = t >> 5, lane = t & 31;
    int wm = w >> 2, wn = w & 3;        // 2 x 4 warp grid, warp tile 64x32

    __shared__ int s_src[128], s_dst[128];
    extern __shared__ __align__(16) char smem[];
    uint32_t smem_u = s2u(smem);

    if (t < 128) {
        int gr = m0 + t;
        if (gr < Mk) {
            int2 rc = g_rows[(z+1)*ROWCAP + gr];
            s_src[t] = rc.x * Dz;
            s_dst[t] = rc.y;
        } else { s_src[t] = 0; s_dst[t] = -1; }
    }
    __syncthreads();

    // loader: thread t -> row t>>1 (0..127), 2x16B at chunk offset (t&1)*2
    int lr = t >> 1, lq = (t & 1) << 1;
    const __nv_bfloat16* gAH = g_featH + s_src[lr] + lq*8;
    const __nv_bfloat16* gAL = g_featL + s_src[lr] + lq*8;
    long wzb = (long)(z*(z+3)/2) * WPER;
    const __nv_bfloat16* gBH = g_WtH + wzb + (long)(n0 + lr) * Ktot + lq*8;
    const __nv_bfloat16* gBL = g_WtL + wzb + (long)(n0 + lr) * Ktot + lq*8;
    uint32_t srow = (uint32_t)lr * 80 + (uint32_t)lq * 16;

    // ldmatrix per-lane bases (within a tile)
    int l8 = lane & 7;
    uint32_t aoff = (uint32_t)(wm*64 + l8 + ((lane >> 3) & 1) * 8) * 80 + ((lane >> 4) & 1) * 16;
    uint32_t boff = (uint32_t)(wn*32 + l8) * 80 + ((lane >> 3) & 1) * 16;

    float acc[4][4][4];
    #pragma unroll
    for (int i = 0; i < 4; i++)
        #pragma unroll
        for (int j = 0; j < 4; j++)
            #pragma unroll
            for (int r = 0; r < 4; r++) acc[i][j][r] = 0.f;

    int nch = Ktot / 32;

    // prologue: chunk 0 -> stage 0
    {
        uint32_t sb = smem_u;
        cpasync16(sb + 0*TILE_B + srow,      gAH);     cpasync16(sb + 0*TILE_B + srow + 16, gAH + 8);
        cpasync16(sb + 1*TILE_B + srow,      gAL);     cpasync16(sb + 1*TILE_B + srow + 16, gAL + 8);
        cpasync16(sb + 2*TILE_B + srow,      gBH);     cpasync16(sb + 2*TILE_B + srow + 16, gBH + 8);
        cpasync16(sb + 3*TILE_B + srow,      gBL);     cpasync16(sb + 3*TILE_B + srow + 16, gBL + 8);
        asm volatile("cp.async.commit_group;" ::: "memory");
    }

    #pragma unroll 1
    for (int c = 0; c < nch; c++) {
        uint32_t sb = smem_u + (uint32_t)(c & 1) * STAGE_B;
        __syncthreads();                          // all warps done with stage (c&1)'s old data
        if (c + 1 < nch) {
            uint32_t nb = smem_u + (uint32_t)((c + 1) & 1) * STAGE_B;
            int ko = (c + 1) * 32;
            cpasync16(nb + 0*TILE_B + srow,      gAH + ko); cpasync16(nb + 0*TILE_B + srow + 16, gAH + ko + 8);
            cpasync16(nb + 1*TILE_B + srow,      gAL + ko); cpasync16(nb + 1*TILE_B + srow + 16, gAL + ko + 8);
            cpasync16(nb + 2*TILE_B + srow,      gBH + ko); cpasync16(nb + 2*TILE_B + srow + 16, gBH + ko + 8);
            cpasync16(nb + 3*TILE_B + srow,      gBL + ko); cpasync16(nb + 3*TILE_B + srow + 16, gBL + ko + 8);
        }
        asm volatile("cp.async.commit_group;" ::: "memory");
        asm volatile("cp.async.wait_group 1;" ::: "memory");   // chunk c complete
        __syncthreads();                          // visibility across warps

        #pragma unroll
        for (int ks = 0; ks < 2; ks++) {
            uint32_t kb = (uint32_t)ks * 32;
            uint32_t ah[4][4], bh[4][2];
            #pragma unroll
            for (int mf = 0; mf < 4; mf++) ldsm4(ah[mf], sb + 0*TILE_B + aoff + mf*16*80 + kb);
            #pragma unroll
            for (int nf = 0; nf < 4; nf++) ldsm2(bh[nf], sb + 2*TILE_B + boff + nf*8*80 + kb);
            #pragma unroll
            for (int mf = 0; mf < 4; mf++)
                #pragma unroll
                for (int nf = 0; nf < 4; nf++) mma16816(acc[mf][nf], ah[mf], bh[nf]);

            uint32_t bl[4][2];
            #pragma unroll
            for (int nf = 0; nf < 4; nf++) ldsm2(bl[nf], sb + 3*TILE_B + boff + nf*8*80 + kb);
            #pragma unroll
            for (int mf = 0; mf < 4; mf++)
                #pragma unroll
                for (int nf = 0; nf < 4; nf++) mma16816(acc[mf][nf], ah[mf], bl[nf]);

            uint32_t al[4][4];
            #pragma unroll
            for (int mf = 0; mf < 4; mf++) ldsm4(al[mf], sb + 1*TILE_B + aoff + mf*16*80 + kb);
            #pragma unroll
            for (int mf = 0; mf < 4; mf++)
                #pragma unroll
                for (int nf = 0; nf < 4; nf++) mma16816(acc[mf][nf], al[mf], bh[nf]);
        }
    }
    asm volatile("cp.async.wait_group 0;" ::: "memory");

    // epilogue: bias + scatter to gathered dst rows
    int r0 = wm*64 + (lane >> 2);
    int cb = n0 + wn*32 + ((lane & 3) << 1);
    const float* bpz = bias.p[z];
    #pragma unroll
    for (int mf = 0; mf < 4; mf++) {
        int row = r0 + mf*16;
        int d0 = s_dst[row], d1 = s_dst[row + 8];
        #pragma unroll
        for (int nf = 0; nf < 4; nf++) {
            float2 bv = *(const float2*)(bpz + cb + nf*8);
            if (d0 >= 0) {
                float2 v; v.x = acc[mf][nf][0] + bv.x; v.y = acc[mf][nf][1] + bv.y;
                *(float2*)(out + (long)d0*Dz + cb + nf*8) = v;
            }
            if (d1 >= 0) {
                float2 v; v.x = acc[mf][nf][2] + bv.x; v.y = acc[mf][nf][3] + bv.y;
                *(float2*)(out + (long)d1*Dz + cb + nf*8) = v;
            }
        }
    }
}

// ---------------- launch ----------------
extern "C" void kernel_launch(void* const* d_in, const int* in_sizes, int n_in,
                              void* d_out, int out_size) {
    const float* feat = (const float*)d_in[0];
    const int*   mask = (const int*)d_in[1];
    // d_in[2] = span_mask (unused; shape only)

    // classify by element count: bias = 768 elems, weight = k*768*768 (ascending k)
    Ptrs7 wp, bp;
    int wi = 0, bi = 0;
    for (int i = 3; i < n_in && i < 17; i++) {
        if (in_sizes[i] == Dz) { if (bi < 7) bp.p[bi++] = (const float*)d_in[i]; }
        else                   { if (wi < 7) wp.p[wi++] = (const float*)d_in[i]; }
    }
    float* out = (float*)d_out;

    int n4 = out_size >> 2;
    prep<<<2048, 256>>>(feat, wp, (float4*)d_out, n4);                 // launch 1

    setup_kernel<<<1, 64>>>(mask);                                     // launch 2

    int tail = (out_size >= Bz*Sz*Dz + Bz*Sz) ? 1 : 0;
    build_rows<<<(Bz*Sz + 255) / 256, 256>>>(out + (size_t)Bz*Sz*Dz, tail);  // launch 3

    cudaFuncSetAttribute(mma_gemm, cudaFuncAttributeMaxDynamicSharedMemorySize, 2*STAGE_B);
    mma_gemm<<<dim3(6, 50, 7), 256, 2*STAGE_B>>>(bp, out);             // launch 4 (profiled)

    copy_k0<<<Bz*(Lz - 2), 192>>>(feat, out);                          // launch 5
}

// round 7
// speedup vs baseline: 2.5495x; 1.1192x over previous
#include <cuda_runtime.h>
#include <cuda_bf16.h>
#include <cstdint>

#define Bz 32
#define Lz 200
#define Dz 768
#define Sz 1556
#define ROWCAP (Bz*Lz)
#define FEATN (Bz*Lz*Dz)
#define WPER  (Dz*Dz)

// ---------------- device scratch (static, no allocs) ----------------
__device__ int  g_offsets[Bz*9];
__device__ int  g_rowbase[8*Bz];
__device__ int  g_Mk[8];
__device__ int2 g_rows[8*ROWCAP];
__device__ __nv_bfloat16 g_featH[FEATN];
__device__ __nv_bfloat16 g_featL[FEATN];
#define WTOT (35*WPER)
__device__ __nv_bfloat16 g_WtH[WTOT];             // K-major [z][o][kk]
__device__ __nv_bfloat16 g_WtL[WTOT];

struct Ptrs7 { const float* p[7]; };

// ---------------- helpers ----------------
__device__ __forceinline__ uint32_t s2u(const void* p) {
    uint32_t a;
    asm("{ .reg .u64 t; cvta.to.shared.u64 t, %1; cvt.u32.u64 %0, t; }" : "=r"(a) : "l"(p));
    return a;
}
__device__ __forceinline__ void cpasync16(uint32_t s, const void* g) {
    asm volatile("cp.async.cg.shared.global [%0], [%1], 16;" :: "r"(s), "l"(g));
}
__device__ __forceinline__ void ldsm4(uint32_t* r, uint32_t a) {
    asm volatile("ldmatrix.sync.aligned.m8n8.x4.shared.b16 {%0,%1,%2,%3}, [%4];"
        : "=r"(r[0]), "=r"(r[1]), "=r"(r[2]), "=r"(r[3]) : "r"(a));
}
__device__ __forceinline__ void ldsm2(uint32_t* r, uint32_t a) {
    asm volatile("ldmatrix.sync.aligned.m8n8.x2.shared.b16 {%0,%1}, [%2];"
        : "=r"(r[0]), "=r"(r[1]) : "r"(a));
}
__device__ __forceinline__ void mma16816(float* c, const uint32_t* a, const uint32_t* b) {
    asm volatile("mma.sync.aligned.m16n8k16.row.col.f32.bf16.bf16.f32 "
        "{%0,%1,%2,%3}, {%4,%5,%6,%7}, {%8,%9}, {%0,%1,%2,%3};"
        : "+f"(c[0]), "+f"(c[1]), "+f"(c[2]), "+f"(c[3])
        : "r"(a[0]), "r"(a[1]), "r"(a[2]), "r"(a[3]), "r"(b[0]), "r"(b[1]));
}

// ---------------- fused prep: zero out + split features + split weights ----------------
__global__ void prep(const float* __restrict__ feat, Ptrs7 w,
                     float4* __restrict__ out4, int n4) {
    int stride = gridDim.x * blockDim.x;
    int tid = blockIdx.x * blockDim.x + threadIdx.x;
    for (int i = tid; i < n4; i += stride)
        out4[i] = make_float4(0.f, 0.f, 0.f, 0.f);
    for (int i = tid; i < FEATN; i += stride) {
        float v = feat[i];
        __nv_bfloat16 h = __float2bfloat16(v);
        g_featH[i] = h;
        g_featL[i] = __float2bfloat16(v - __bfloat162float(h));
    }
    for (long i = tid; i < (long)WTOT; i += stride) {
        long r = i; int z = 0;
        while (r >= (long)(z + 2) * WPER) { r -= (long)(z + 2) * WPER; z++; }
        int K = Dz * (z + 2);
        int o = (int)(r / K), kk = (int)(r % K);
        int j = kk / Dz, ii = kk - j * Dz;
        float v = w.p[z][(long)o * K + ii * (z + 2) + j];
        __nv_bfloat16 h = __float2bfloat16(v);
        long dst = (long)(z * (z + 3) / 2) * WPER + r;
        g_WtH[dst] = h;
        g_WtL[dst] = __float2bfloat16(v - __bfloat162float(h));
    }
}

// ---------------- setup: lengths, offsets, per-k bases ----------------
__global__ void setup_kernel(const int* __restrict__ mask) {
    __shared__ int sh_n[Bz];
    int t = threadIdx.x;
    if (t < Bz) {
        int n = 0;
        #pragma unroll 8
        for (int i = 0; i < Lz; i++) n += mask[t*Lz + i];
        sh_n[t] = n;
        int off = 0;
        g_offsets[t*9 + 0] = 0;
        #pragma unroll
        for (int k = 0; k < 8; k++) {
            int c = n - k - 2; if (c < 0) c = 0;
            off += c;
            g_offsets[t*9 + k + 1] = off;
        }
    }
    __syncthreads();
    if (t < 8) {
        int k = t, run = 0;
        for (int b = 0; b < Bz; b++) {
            g_rowbase[k*Bz + b] = run;
            int c = sh_n[b] - k - 2; if (c < 0) c = 0;
            run += c;
        }
        g_Mk[k] = run;
    }
}

// ---------------- per-slot bucket/pos, build row lists ----------------
__global__ void build_rows(float* __restrict__ out_tail, int write_tail) {
    int idx = blockIdx.x * blockDim.x + threadIdx.x;
    if (idx >= Bz*Sz) return;
    int b = idx / Sz, s = idx % Sz;
    const int* off = &g_offsets[b*9];
    int k = 0;
    #pragma unroll
    for (int m = 1; m < 8; m++) k += (off[m] <= s);
    if (s < off[8]) {
        int rel = s - off[k];
        int p = rel + 1;
        int r = g_rowbase[k*Bz + b] + rel;
        g_rows[k*ROWCAP + r] = make_int2(b*Lz + p, idx);
        if (write_tail) out_tail[idx] = 1.0f;
    }
}

// ---------------- bucket 0: exact fp32 row copy ----------------
__global__ void copy_k0(const float* __restrict__ feat, float* __restrict__ out) {
    int r = blockIdx.x;
    if (r >= g_Mk[0]) return;
    int2 rc = g_rows[r];
    const float4* __restrict__ s = (const float4*)(feat + (size_t)rc.x * Dz);
    float4* __restrict__ d = (float4*)(out + (size_t)rc.y * Dz);
    d[threadIdx.x] = s[threadIdx.x];
}

// ---------------- mma.sync gathered GEMM, buckets k=1..7 ----------------
// K-chunk 32 bf16 (64B rows, packed + XOR swizzle c^=(row>>1)&3), 3-stage cp.async,
// one __syncthreads per chunk. Split terms per chunk: D += AH*BH + AH*BL + AL*BH.
#define TILE_B  8192
#define STAGE_B 32768
#define SMEMREQ (3*STAGE_B + 128)
__global__ void __launch_bounds__(256, 2) mma_gemm(Ptrs7 bias, float* __restrict__ out) {
    int z = 6 - blockIdx.z;             // heavy buckets (large Ktot) first
    int Mk = g_Mk[z + 1];
    int m0 = blockIdx.y * 128;
    if (m0 >= Mk) return;
    int Ktot = Dz * (z + 2);
    int n0 = blockIdx.x * 128;
    int t = threadIdx.x;
    int w = t >> 5, lane = t & 31;
    int wm = w >> 2, wn = w & 3;        // 2 x 4 warp grid, warp tile 64x32

    __shared__ int s_src[128], s_dst[128];
    extern __shared__ __align__(16) char smem[];
    uint32_t smem_u = (s2u(smem) + 127) & ~127u;

    if (t < 128) {
        int gr = m0 + t;
        if (gr < Mk) {
            int2 rc = g_rows[(z+1)*ROWCAP + gr];
            s_src[t] = rc.x * Dz;
            s_dst[t] = rc.y;
        } else { s_src[t] = 0; s_dst[t] = -1; }
    }
    __syncthreads();

    // loader: thread t -> row t>>1, 16B chunks cq, cq+1 (cq = (t&1)*2)
    int lr = t >> 1;
    int cq = (t & 1) << 1;
    int swb = (lr >> 1) & 3;
    uint32_t off0 = (uint32_t)lr * 64 + (uint32_t)((cq     ^ swb) << 4);
    uint32_t off1 = (uint32_t)lr * 64 + (uint32_t)(((cq+1) ^ swb) << 4);
    const __nv_bfloat16* gAH = g_featH + s_src[lr] + cq*8;
    const __nv_bfloat16* gAL = g_featL + s_src[lr] + cq*8;
    long wzb = (long)(z*(z+3)/2) * WPER;
    const __nv_bfloat16* gBH = g_WtH + wzb + (long)(n0 + lr) * Ktot + cq*8;
    const __nv_bfloat16* gBL = g_WtL + wzb + (long)(n0 + lr) * Ktot + cq*8;

    // ldmatrix per-lane bases: swizzle index is invariant across mf/nf steps
    int l8 = lane & 7;
    int rowA = wm*64 + l8 + ((lane >> 3) & 1) * 8;
    int rowB = wn*32 + l8;
    uint32_t swzA = (uint32_t)((rowA >> 1) & 3);
    uint32_t swzB = (uint32_t)((rowB >> 1) & 3);
    uint32_t cA0 = (lane >> 4) & 1;
    uint32_t cB0 = (lane >> 3) & 1;
    uint32_t aRow[4], bRow[4];
    #pragma unroll
    for (int mf = 0; mf < 4; mf++) aRow[mf] = (uint32_t)(rowA + mf*16) * 64;
    #pragma unroll
    for (int nf = 0; nf < 4; nf++) bRow[nf] = (uint32_t)(rowB + nf*8) * 64;

    float acc[4][4][4];
    #pragma unroll
    for (int i = 0; i < 4; i++)
        #pragma unroll
        for (int j = 0; j < 4; j++)
            #pragma unroll
            for (int r = 0; r < 4; r++) acc[i][j][r] = 0.f;

    int nch = Ktot / 32;

    // prologue: chunks 0,1 -> stages 0,1
    #pragma unroll
    for (int p = 0; p < 2; p++) {
        uint32_t sb = smem_u + (uint32_t)p * STAGE_B;
        int ko = p * 32;
        cpasync16(sb + 0*TILE_B + off0, gAH + ko); cpasync16(sb + 0*TILE_B + off1, gAH + ko + 8);
        cpasync16(sb + 1*TILE_B + off0, gAL + ko); cpasync16(sb + 1*TILE_B + off1, gAL + ko + 8);
        cpasync16(sb + 2*TILE_B + off0, gBH + ko); cpasync16(sb + 2*TILE_B + off1, gBH + ko + 8);
        cpasync16(sb + 3*TILE_B + off0, gBL + ko); cpasync16(sb + 3*TILE_B + off1, gBL + ko + 8);
        asm volatile("cp.async.commit_group;" ::: "memory");
    }

    int stg = 0;                        // stage index of chunk c (mod 3)
    int pstg = 2;                       // stage index of chunk c+2
    #pragma unroll 1
    for (int c = 0; c < nch; c++) {
        asm volatile("cp.async.wait_group 1;" ::: "memory");   // chunk c landed
        __syncthreads();                                       // visible; frees stage pstg
        if (c + 2 < nch) {
            uint32_t nb = smem_u + (uint32_t)pstg * STAGE_B;
            int ko = (c + 2) * 32;
            cpasync16(nb + 0*TILE_B + off0, gAH + ko); cpasync16(nb + 0*TILE_B + off1, gAH + ko + 8);
            cpasync16(nb + 1*TILE_B + off0, gAL + ko); cpasync16(nb + 1*TILE_B + off1, gAL + ko + 8);
            cpasync16(nb + 2*TILE_B + off0, gBH + ko); cpasync16(nb + 2*TILE_B + off1, gBH + ko + 8);
            cpasync16(nb + 3*TILE_B + off0, gBL + ko); cpasync16(nb + 3*TILE_B + off1, gBL + ko + 8);
        }
        asm volatile("cp.async.commit_group;" ::: "memory");

        uint32_t sb = smem_u + (uint32_t)stg * STAGE_B;
        #pragma unroll
        for (int ks = 0; ks < 2; ks++) {
            uint32_t colA = ((cA0 + 2*ks) ^ swzA) << 4;
            uint32_t colB = ((cB0 + 2*ks) ^ swzB) << 4;
            uint32_t ah[4][4], bh[4][2];
            #pragma unroll
            for (int mf = 0; mf < 4; mf++) ldsm4(ah[mf], sb + 0*TILE_B + aRow[mf] + colA);
            #pragma unroll
            for (int nf = 0; nf < 4; nf++) ldsm2(bh[nf], sb + 2*TILE_B + bRow[nf] + colB);
            #pragma unroll
            for (int mf = 0; mf < 4; mf++)
                #pragma unroll
                for (int nf = 0; nf < 4; nf++) mma16816(acc[mf][nf], ah[mf], bh[nf]);

            uint32_t bl[4][2];
            #pragma unroll
            for (int nf = 0; nf < 4; nf++) ldsm2(bl[nf], sb + 3*TILE_B + bRow[nf] + colB);
            #pragma unroll
            for (int mf = 0; mf < 4; mf++)
                #pragma unroll
                for (int nf = 0; nf < 4; nf++) mma16816(acc[mf][nf], ah[mf], bl[nf]);

            uint32_t al[4][4];
            #pragma unroll
            for (int mf = 0; mf < 4; mf++) ldsm4(al[mf], sb + 1*TILE_B + aRow[mf] + colA);
            #pragma unroll
            for (int mf = 0; mf < 4; mf++)
                #pragma unroll
                for (int nf = 0; nf < 4; nf++) mma16816(acc[mf][nf], al[mf], bh[nf]);
        }
        stg = (stg == 2) ? 0 : stg + 1;
        pstg = (pstg == 2) ? 0 : pstg + 1;
    }
    asm volatile("cp.async.wait_group 0;" ::: "memory");

    // epilogue: bias + scatter to gathered dst rows
    int r0 = wm*64 + (lane >> 2);
    int cb = n0 + wn*32 + ((lane & 3) << 1);
    const float* bpz = bias.p[z];
    #pragma unroll
    for (int mf = 0; mf < 4; mf++) {
        int row = r0 + mf*16;
        int d0 = s_dst[row], d1 = s_dst[row + 8];
        #pragma unroll
        for (int nf = 0; nf < 4; nf++) {
            float2 bv = *(const float2*)(bpz + cb + nf*8);
            if (d0 >= 0) {
                float2 v; v.x = acc[mf][nf][0] + bv.x; v.y = acc[mf][nf][1] + bv.y;
                *(float2*)(out + (long)d0*Dz + cb + nf*8) = v;
            }
            if (d1 >= 0) {
                float2 v; v.x = acc[mf][nf][2] + bv.x; v.y = acc[mf][nf][3] + bv.y;
                *(float2*)(out + (long)d1*Dz + cb + nf*8) = v;
            }
        }
    }
}

// ---------------- launch ----------------
extern "C" void kernel_launch(void* const* d_in, const int* in_sizes, int n_in,
                              void* d_out, int out_size) {
    const float* feat = (const float*)d_in[0];
    const int*   mask = (const int*)d_in[1];
    // d_in[2] = span_mask (unused; shape only)

    // classify by element count: bias = 768 elems, weight = k*768*768 (ascending k)
    Ptrs7 wp, bp;
    int wi = 0, bi = 0;
    for (int i = 3; i < n_in && i < 17; i++) {
        if (in_sizes[i] == Dz) { if (bi < 7) bp.p[bi++] = (const float*)d_in[i]; }
        else                   { if (wi < 7) wp.p[wi++] = (const float*)d_in[i]; }
    }
    float* out = (float*)d_out;

    int n4 = out_size >> 2;
    prep<<<2048, 256>>>(feat, wp, (float4*)d_out, n4);                 // launch 1

    setup_kernel<<<1, 64>>>(mask);                                     // launch 2

    int tail = (out_size >= Bz*Sz*Dz + Bz*Sz) ? 1 : 0;
    build_rows<<<(Bz*Sz + 255) / 256, 256>>>(out + (size_t)Bz*Sz*Dz, tail);  // launch 3

    cudaFuncSetAttribute(mma_gemm, cudaFuncAttributeMaxDynamicSharedMemorySize, SMEMREQ);
    mma_gemm<<<dim3(6, 50, 7), 256, SMEMREQ>>>(bp, out);               // launch 4 (profiled)

    copy_k0<<<Bz*(Lz - 2), 192>>>(feat, out);                          // launch 5
}